// round 13
// baseline (speedup 1.0000x reference)
#include <cuda_runtime.h>
#include <cuda_fp16.h>
#include <math.h>
#include <stdint.h>

#define NTOK 4096   // B*T
#define DD   1024   // model dim
#define NE   8      // experts
#define FF   4096   // ffn dim

// ---------------- device scratch ----------------
__device__ int    g_cnt[NE];          // statically zero; combine re-zeros each run
__device__ int    g_list[NE * NTOK];
__device__ int    g_cp[NTOK * 2];
__device__ float  g_cw[NTOK * 2];
__device__ __half g_Xh[(size_t)NTOK * DD];
__device__ __half g_W1h[(size_t)NE * DD * FF];
__device__ __half g_W2h[(size_t)NE * FF * DD];
__device__ __half g_H[(size_t)NE * NTOK * FF];
__device__ float  g_Y[(size_t)NE * NTOK * DD];

// ---------------- fp32 -> fp16 conversion ----------------
__global__ void f2h_kernel(const float* __restrict__ src, __half* __restrict__ dst,
                           int n4) {
    int stride = gridDim.x * blockDim.x;
    for (int i = blockIdx.x * blockDim.x + threadIdx.x; i < n4; i += stride) {
        float4 v = ((const float4*)src)[i];
        __half2 h0 = __halves2half2(__float2half_rn(v.x), __float2half_rn(v.y));
        __half2 h1 = __halves2half2(__float2half_rn(v.z), __float2half_rn(v.w));
        uint2 u;
        u.x = *(uint32_t*)&h0;
        u.y = *(uint32_t*)&h1;
        ((uint2*)dst)[i] = u;
    }
}

// ---------------- gating (fp32 top-k) + fused x fp16 conversion ----------------
__global__ void gate_kernel(const float* __restrict__ x,
                            const float* __restrict__ gw,
                            const float* __restrict__ gb,
                            float* gate_logits, float* topk) {
    __shared__ float xs[DD];
    __shared__ float lg[NE];
    int t = blockIdx.x;
    const float4* xr = (const float4*)(x + (size_t)t * DD);
    for (int i = threadIdx.x; i < DD / 4; i += blockDim.x)
        ((float4*)xs)[i] = xr[i];
    __syncthreads();

    {
        int i = threadIdx.x;              // 256 threads == DD/4 chunks
        float4 v = ((const float4*)xs)[i];
        __half2 h0 = __halves2half2(__float2half_rn(v.x), __float2half_rn(v.y));
        __half2 h1 = __halves2half2(__float2half_rn(v.z), __float2half_rn(v.w));
        uint2 u;
        u.x = *(uint32_t*)&h0;
        u.y = *(uint32_t*)&h1;
        ((uint2*)(g_Xh + (size_t)t * DD))[i] = u;
    }

    int w = threadIdx.x >> 5, lane = threadIdx.x & 31;
    float s = 0.f;
    for (int j = lane; j < DD; j += 32) s += xs[j] * gw[j * NE + w];
#pragma unroll
    for (int o = 16; o; o >>= 1) s += __shfl_xor_sync(0xffffffffu, s, o);
    if (lane == 0) lg[w] = s + gb[w];
    __syncthreads();

    if (threadIdx.x == 0) {
        float v[NE];
#pragma unroll
        for (int e = 0; e < NE; e++) v[e] = lg[e];
        int i0 = 0;
        for (int e = 1; e < NE; e++) if (v[e] > v[i0]) i0 = e;
        int i1 = -1;
        for (int e = 0; e < NE; e++) {
            if (e == i0) continue;
            if (i1 < 0 || v[e] > v[i1]) i1 = e;
        }
        float ew = expf(v[i1] - v[i0]);
        float w0 = 1.f / (1.f + ew);
        float w1 = ew / (1.f + ew);

        int p0 = atomicAdd(&g_cnt[i0], 1);
        g_list[i0 * NTOK + p0] = t;
        int p1 = atomicAdd(&g_cnt[i1], 1);
        g_list[i1 * NTOK + p1] = t;
        g_cp[t * 2] = i0 * NTOK + p0;  g_cw[t * 2] = w0;
        g_cp[t * 2 + 1] = i1 * NTOK + p1;  g_cw[t * 2 + 1] = w1;

        if (gate_logits)
            for (int e = 0; e < NE; e++) gate_logits[(size_t)t * NE + e] = v[e];
        if (topk) { topk[t * 2] = (float)i0; topk[t * 2 + 1] = (float)i1; }
    }
}

// ---------------- helpers ----------------
__device__ __forceinline__ uint32_t smem_u32(const void* p) {
    uint32_t a;
    asm("{ .reg .u64 t; cvta.to.shared.u64 t, %1; cvt.u32.u64 %0, t; }"
        : "=r"(a) : "l"(p));
    return a;
}
__device__ __forceinline__ void mma16(float* c, const uint32_t* a, const uint32_t* b) {
    asm volatile(
        "mma.sync.aligned.m16n8k16.row.col.f32.f16.f16.f32 "
        "{%0,%1,%2,%3}, {%4,%5,%6,%7}, {%8,%9}, {%0,%1,%2,%3};"
        : "+f"(c[0]), "+f"(c[1]), "+f"(c[2]), "+f"(c[3])
        : "r"(a[0]), "r"(a[1]), "r"(a[2]), "r"(a[3]), "r"(b[0]), "r"(b[1]));
}
__device__ __forceinline__ float gelu(float v) {
    return 0.5f * v * (1.f + erff(v * 0.70710678118654752f));
}
#define CP16(dst, src) \
    asm volatile("cp.async.cg.shared.global [%0], [%1], 16;" :: "r"(dst), "l"(src))
#define CP_COMMIT() asm volatile("cp.async.commit_group;" ::: "memory")
#define CP_WAIT2() asm volatile("cp.async.wait_group 2;" ::: "memory")

// ---------------- fp16 sparse per-expert GEMM (exact R11/504us kernel, ----------------
// ---------------- per-expert launch: e passed as argument)              ----------------
// block 128x128, 128 threads, 2x2 warps (64x64 warp tile), BK=32, 4-stage cp.async
// MODE 1: A = gathered g_Xh rows -> gelu -> g_H (fp16)
// MODE 2: A = g_H rows -> +bias -> g_Y (fp32)
template <int KTOT, int LDB, int MODE>
__global__ void __launch_bounds__(128, 2)
moe_gemm(const __half* __restrict__ Bh, const float* __restrict__ bias, int e) {
    constexpr int BK = 32;
    constexpr int KIT = KTOT / BK;
    constexpr int SA_ST = 10240, SB_ST = 8704;
    constexpr int OFF_B = 4 * SA_ST;            // 40960
    constexpr int OFF_TOK = OFF_B + 4 * SB_ST;  // 75776
    extern __shared__ __align__(16) char smem[];
    const uint32_t sbase = smem_u32(smem);

    const int cnt = g_cnt[e];
    const int m0 = blockIdx.y * 128;
    if (m0 >= cnt) return;
    const int n0 = blockIdx.x * 128;
    const int rows = min(cnt - m0, 128);
    const int tid = threadIdx.x, lane = tid & 31, wid = tid >> 5;
    const int wm = wid >> 1, wn = wid & 1;

    int* sTok = (int*)(smem + OFF_TOK);
    if (MODE == 1) {
        if (tid < 128) sTok[tid] = g_list[e * NTOK + m0 + min(tid, rows - 1)];
        __syncthreads();
    }

    const __half* pA[4]; uint32_t aOfs[4];
#pragma unroll
    for (int i = 0; i < 4; i++) {
        int idx = tid + i * 128, r = idx >> 2, c = idx & 3;
        size_t rb;
        if (MODE == 1) rb = (size_t)sTok[r] * DD;
        else           rb = ((size_t)e * NTOK + m0 + r) * FF;
        pA[i] = ((MODE == 1) ? g_Xh : g_H) + rb + c * 8;
        aOfs[i] = (uint32_t)(r * 80 + c * 16);
    }
    const __half* pB[4]; uint32_t bOfs[4];
#pragma unroll
    for (int i = 0; i < 4; i++) {
        int idx = tid + i * 128, k = idx >> 4, c = idx & 15;
        pB[i] = Bh + (size_t)e * KTOT * LDB + (size_t)k * LDB + n0 + c * 8;
        bOfs[i] = (uint32_t)(k * 272 + c * 16);
    }

    uint32_t aFrag[4];
#pragma unroll
    for (int ms = 0; ms < 4; ms++) {
        int row = wm * 64 + ms * 16 + (lane & 7) + ((lane >> 3) & 1) * 8;
        aFrag[ms] = (uint32_t)(row * 80 + ((lane >> 4) & 1) * 16);
    }
    uint32_t bFrag[4];
#pragma unroll
    for (int p = 0; p < 4; p++) {
        int k = (lane & 7) + ((lane >> 3) & 1) * 8;
        int n = wn * 64 + p * 16 + ((lane >> 4) & 1) * 8;
        bFrag[p] = (uint32_t)(k * 272 + n * 2);
    }

    float acc[4][8][4];
#pragma unroll
    for (int a = 0; a < 4; a++)
#pragma unroll
        for (int b = 0; b < 8; b++)
#pragma unroll
            for (int r = 0; r < 4; r++) acc[a][b][r] = 0.f;

    auto fill = [&](int kt) {
        int st = kt & 3;
        uint32_t sa = sbase + st * SA_ST;
        uint32_t sb = sbase + OFF_B + st * SB_ST;
#pragma unroll
        for (int i = 0; i < 4; i++)
            CP16(sa + aOfs[i], pA[i] + (size_t)kt * BK);
#pragma unroll
        for (int i = 0; i < 4; i++)
            CP16(sb + bOfs[i], pB[i] + (size_t)kt * BK * LDB);
    };
    auto compute = [&](int kt) {
        int st = kt & 3;
        uint32_t sa = sbase + st * SA_ST;
        uint32_t sb = sbase + OFF_B + st * SB_ST;
#pragma unroll
        for (int s = 0; s < 2; s++) {
            uint32_t af[4][4], bf[8][2];
#pragma unroll
            for (int ms = 0; ms < 4; ms++) {
                uint32_t addr = sa + aFrag[ms] + s * 32;
                asm volatile(
                    "ldmatrix.sync.aligned.m8n8.x4.shared.b16 {%0,%1,%2,%3}, [%4];"
                    : "=r"(af[ms][0]), "=r"(af[ms][1]),
                      "=r"(af[ms][2]), "=r"(af[ms][3]) : "r"(addr));
            }
#pragma unroll
            for (int p = 0; p < 4; p++) {
                uint32_t addr = sb + bFrag[p] + s * (16 * 272);
                asm volatile(
                    "ldmatrix.sync.aligned.m8n8.x4.trans.shared.b16 {%0,%1,%2,%3}, [%4];"
                    : "=r"(bf[2 * p][0]), "=r"(bf[2 * p][1]),
                      "=r"(bf[2 * p + 1][0]), "=r"(bf[2 * p + 1][1]) : "r"(addr));
            }
#pragma unroll
            for (int ms = 0; ms < 4; ms++)
#pragma unroll
                for (int ns = 0; ns < 8; ns++)
                    mma16(acc[ms][ns], af[ms], bf[ns]);
        }
    };

    fill(0); CP_COMMIT();
    fill(1); CP_COMMIT();
    fill(2); CP_COMMIT();
    for (int kt = 0; kt < KIT; kt++) {
        CP_WAIT2();
        __syncthreads();
        if (kt + 3 < KIT) fill(kt + 3);
        CP_COMMIT();
        compute(kt);
    }

    constexpr int ND = (MODE == 1) ? FF : DD;
    const int lr = lane >> 2, lc = lane & 3;
#pragma unroll
    for (int ms = 0; ms < 4; ms++) {
#pragma unroll
        for (int half = 0; half < 2; half++) {
            int r = wm * 64 + ms * 16 + lr + half * 8;
            if (r >= rows) continue;
            size_t rowb = ((size_t)e * NTOK + m0 + r) * ND;
#pragma unroll
            for (int ns = 0; ns < 8; ns++) {
                int col = n0 + wn * 64 + ns * 8 + lc * 2;
                float2 bv = *(const float2*)&bias[(size_t)e * ND + col];
                float v0 = acc[ms][ns][half * 2 + 0] + bv.x;
                float v1 = acc[ms][ns][half * 2 + 1] + bv.y;
                if (MODE == 1) {
                    v0 = gelu(v0); v1 = gelu(v1);
                    *(__half2*)&g_H[rowb + col] =
                        __halves2half2(__float2half_rn(v0), __float2half_rn(v1));
                } else {
                    *(float2*)&g_Y[rowb + col] = make_float2(v0, v1);
                }
            }
        }
    }
}

// ---------------- combine + expert_counts + counter reset ----------------
__global__ void combine_kernel(float* __restrict__ out, float* __restrict__ counts) {
    int t = blockIdx.x;
    int i = threadIdx.x;
    if (t == 0 && i < NE) {
        if (counts) counts[i] = (float)g_cnt[i];
        g_cnt[i] = 0;
    }
    int p0 = g_cp[t * 2], p1 = g_cp[t * 2 + 1];
    float w0 = g_cw[t * 2], w1 = g_cw[t * 2 + 1];
    const float4* y0 = (const float4*)(g_Y + (size_t)p0 * DD);
    const float4* y1 = (const float4*)(g_Y + (size_t)p1 * DD);
    float4 a = y0[i], b = y1[i], r;
    r.x = w0 * a.x + w1 * b.x;
    r.y = w0 * a.y + w1 * b.y;
    r.z = w0 * a.z + w1 * b.z;
    r.w = w0 * a.w + w1 * b.w;
    ((float4*)(out + (size_t)t * DD))[i] = r;
}

// ---------------- launch: per-expert GEMM1/GEMM2 pipelined across streams --------
extern "C" void kernel_launch(void* const* d_in, const int* in_sizes, int n_in,
                              void* d_out, int out_size) {
    const float* x  = (const float*)d_in[0];
    const float* gw = (const float*)d_in[1];
    const float* gb = (const float*)d_in[2];
    const float* w1 = (const float*)d_in[3];
    const float* b1 = (const float*)d_in[4];
    const float* w2 = (const float*)d_in[5];
    const float* b2 = (const float*)d_in[6];
    float* out = (float*)d_out;

    const long long OUT0 = (long long)NTOK * DD;
    long long os = out_size;
    float* gl = nullptr; float* tk = nullptr; float* cn = nullptr;
    if (os >= OUT0 + (long long)NTOK * NE)
        gl = out + OUT0;
    if (os >= OUT0 + (long long)NTOK * NE + NTOK * 2)
        tk = out + OUT0 + (long long)NTOK * NE;
    if (os >= OUT0 + (long long)NTOK * NE + NTOK * 2 + NE)
        cn = out + OUT0 + (long long)NTOK * NE + NTOK * 2;

    static __half* w1h = nullptr; static __half* w2h = nullptr;
    static cudaStream_t s1, s2;
    static cudaEvent_t evFork, evW1, evW2, evG1[NE], evG2;
    static bool init_done = false;
    if (!init_done) {
        cudaGetSymbolAddress((void**)&w1h, g_W1h);
        cudaGetSymbolAddress((void**)&w2h, g_W2h);
        cudaStreamCreateWithFlags(&s1, cudaStreamNonBlocking);
        cudaStreamCreateWithFlags(&s2, cudaStreamNonBlocking);
        cudaEventCreateWithFlags(&evFork, cudaEventDisableTiming);
        cudaEventCreateWithFlags(&evW1, cudaEventDisableTiming);
        cudaEventCreateWithFlags(&evW2, cudaEventDisableTiming);
        cudaEventCreateWithFlags(&evG2, cudaEventDisableTiming);
        for (int e = 0; e < NE; e++)
            cudaEventCreateWithFlags(&evG1[e], cudaEventDisableTiming);
        const int SM_ = 76288;
        cudaFuncSetAttribute(moe_gemm<DD, FF, 1>,
                             cudaFuncAttributeMaxDynamicSharedMemorySize, SM_);
        cudaFuncSetAttribute(moe_gemm<FF, DD, 2>,
                             cudaFuncAttributeMaxDynamicSharedMemorySize, SM_);
        init_done = true;
    }
    const int SMEM = 76288;
    cudaStream_t s0 = 0;

    // fork side streams off capture origin
    cudaEventRecord(evFork, s0);
    cudaStreamWaitEvent(s1, evFork, 0);
    cudaStreamWaitEvent(s2, evFork, 0);

    // s1: weight conversions
    f2h_kernel<<<8192, 256, 0, s1>>>(w1, w1h, NE * DD * FF / 4);
    cudaEventRecord(evW1, s1);
    f2h_kernel<<<8192, 256, 0, s1>>>(w2, w2h, NE * FF * DD / 4);
    cudaEventRecord(evW2, s1);

    // s0: gating, then per-expert GEMM1 chain
    gate_kernel<<<NTOK, 256, 0, s0>>>(x, gw, gb, gl, tk);
    cudaStreamWaitEvent(s0, evW1, 0);
    for (int e = 0; e < NE; e++) {
        moe_gemm<DD, FF, 1><<<dim3(FF / 128, NTOK / 128), 128, SMEM, s0>>>(w1h, b1, e);
        cudaEventRecord(evG1[e], s0);
    }

    // s2: per-expert GEMM2, each gated on its GEMM1 (overlaps GEMM1 of later experts)
    cudaStreamWaitEvent(s2, evW2, 0);
    for (int e = 0; e < NE; e++) {
        cudaStreamWaitEvent(s2, evG1[e], 0);
        moe_gemm<FF, DD, 2><<<dim3(DD / 128, NTOK / 128), 128, SMEM, s2>>>(w2h, b2, e);
    }
    cudaEventRecord(evG2, s2);

    // join back to s0 for combine
    cudaStreamWaitEvent(s0, evG2, 0);
    combine_kernel<<<NTOK, 256, 0, s0>>>(out, cn);
}

// round 14
// speedup vs baseline: 1.5506x; 1.5506x over previous
#include <cuda_runtime.h>
#include <cuda_fp16.h>
#include <math.h>
#include <stdint.h>

#define NTOK 4096   // B*T
#define DD   1024   // model dim
#define NE   8      // experts
#define FF   4096   // ffn dim

// ---------------- device scratch ----------------
__device__ int    g_cnt[NE];          // statically zero; combine re-zeros each run
__device__ int    g_list[NE * NTOK];
__device__ int    g_cp[NTOK * 2];
__device__ float  g_cw[NTOK * 2];
__device__ __half g_Xh[(size_t)NTOK * DD];
__device__ __half g_W1h[(size_t)NE * DD * FF];
__device__ __half g_W2h[(size_t)NE * FF * DD];
__device__ __half g_H[(size_t)NE * NTOK * FF];
__device__ float  g_Y[(size_t)NE * NTOK * DD];

// ---------------- fp32 -> fp16 conversion ----------------
__global__ void f2h_kernel(const float* __restrict__ src, __half* __restrict__ dst,
                           int n4) {
    int stride = gridDim.x * blockDim.x;
    for (int i = blockIdx.x * blockDim.x + threadIdx.x; i < n4; i += stride) {
        float4 v = ((const float4*)src)[i];
        __half2 h0 = __halves2half2(__float2half_rn(v.x), __float2half_rn(v.y));
        __half2 h1 = __halves2half2(__float2half_rn(v.z), __float2half_rn(v.w));
        uint2 u;
        u.x = *(uint32_t*)&h0;
        u.y = *(uint32_t*)&h1;
        ((uint2*)dst)[i] = u;
    }
}

// ---------------- gating (fp32 top-k) + fused x fp16 conversion ----------------
__global__ void gate_kernel(const float* __restrict__ x,
                            const float* __restrict__ gw,
                            const float* __restrict__ gb,
                            float* gate_logits, float* topk) {
    __shared__ float xs[DD];
    __shared__ float lg[NE];
    int t = blockIdx.x;
    const float4* xr = (const float4*)(x + (size_t)t * DD);
    for (int i = threadIdx.x; i < DD / 4; i += blockDim.x)
        ((float4*)xs)[i] = xr[i];
    __syncthreads();

    {
        int i = threadIdx.x;              // 256 threads == DD/4 chunks
        float4 v = ((const float4*)xs)[i];
        __half2 h0 = __halves2half2(__float2half_rn(v.x), __float2half_rn(v.y));
        __half2 h1 = __halves2half2(__float2half_rn(v.z), __float2half_rn(v.w));
        uint2 u;
        u.x = *(uint32_t*)&h0;
        u.y = *(uint32_t*)&h1;
        ((uint2*)(g_Xh + (size_t)t * DD))[i] = u;
    }

    int w = threadIdx.x >> 5, lane = threadIdx.x & 31;
    float s = 0.f;
    for (int j = lane; j < DD; j += 32) s += xs[j] * gw[j * NE + w];
#pragma unroll
    for (int o = 16; o; o >>= 1) s += __shfl_xor_sync(0xffffffffu, s, o);
    if (lane == 0) lg[w] = s + gb[w];
    __syncthreads();

    if (threadIdx.x == 0) {
        float v[NE];
#pragma unroll
        for (int e = 0; e < NE; e++) v[e] = lg[e];
        int i0 = 0;
        for (int e = 1; e < NE; e++) if (v[e] > v[i0]) i0 = e;
        int i1 = -1;
        for (int e = 0; e < NE; e++) {
            if (e == i0) continue;
            if (i1 < 0 || v[e] > v[i1]) i1 = e;
        }
        float ew = expf(v[i1] - v[i0]);
        float w0 = 1.f / (1.f + ew);
        float w1 = ew / (1.f + ew);

        int p0 = atomicAdd(&g_cnt[i0], 1);
        g_list[i0 * NTOK + p0] = t;
        int p1 = atomicAdd(&g_cnt[i1], 1);
        g_list[i1 * NTOK + p1] = t;
        g_cp[t * 2] = i0 * NTOK + p0;  g_cw[t * 2] = w0;
        g_cp[t * 2 + 1] = i1 * NTOK + p1;  g_cw[t * 2 + 1] = w1;

        if (gate_logits)
            for (int e = 0; e < NE; e++) gate_logits[(size_t)t * NE + e] = v[e];
        if (topk) { topk[t * 2] = (float)i0; topk[t * 2 + 1] = (float)i1; }
    }
}

// ---------------- helpers ----------------
__device__ __forceinline__ uint32_t smem_u32(const void* p) {
    uint32_t a;
    asm("{ .reg .u64 t; cvta.to.shared.u64 t, %1; cvt.u32.u64 %0, t; }"
        : "=r"(a) : "l"(p));
    return a;
}
__device__ __forceinline__ void mma16(float* c, const uint32_t* a, const uint32_t* b) {
    asm volatile(
        "mma.sync.aligned.m16n8k16.row.col.f32.f16.f16.f32 "
        "{%0,%1,%2,%3}, {%4,%5,%6,%7}, {%8,%9}, {%0,%1,%2,%3};"
        : "+f"(c[0]), "+f"(c[1]), "+f"(c[2]), "+f"(c[3])
        : "r"(a[0]), "r"(a[1]), "r"(a[2]), "r"(a[3]), "r"(b[0]), "r"(b[1]));
}
__device__ __forceinline__ float gelu(float v) {
    return 0.5f * v * (1.f + erff(v * 0.70710678118654752f));
}
#define CP16(dst, src) \
    asm volatile("cp.async.cg.shared.global [%0], [%1], 16;" :: "r"(dst), "l"(src))
#define CP_COMMIT() asm volatile("cp.async.commit_group;" ::: "memory")
#define CP_WAIT2() asm volatile("cp.async.wait_group 2;" ::: "memory")

// ---------------- fp16 sparse per-expert GEMM, cp.async + ldmatrix ----------------
// block 128x128, 128 threads, 2x2 warps (64x64 warp tile), BK=32, 4-stage cp.async.
// R11 base + slab-level fragment double buffering (hide LDSM latency under HMMA).
// MODE 1: A = gathered g_Xh rows -> gelu -> g_H (fp16)
// MODE 2: A = g_H rows -> +bias -> g_Y (fp32)
template <int KTOT, int LDB, int MODE>
__global__ void __launch_bounds__(128, 2)
moe_gemm(const __half* __restrict__ Bh, const float* __restrict__ bias) {
    constexpr int BK = 32;
    constexpr int KIT = KTOT / BK;
    constexpr int SA_ST = 10240, SB_ST = 8704;
    constexpr int OFF_B = 4 * SA_ST;            // 40960
    constexpr int OFF_TOK = OFF_B + 4 * SB_ST;  // 75776
    extern __shared__ __align__(16) char smem[];
    const uint32_t sbase = smem_u32(smem);

    const int e = blockIdx.z;
    const int cnt = g_cnt[e];
    const int m0 = blockIdx.y * 128;
    if (m0 >= cnt) return;
    const int n0 = blockIdx.x * 128;
    const int rows = min(cnt - m0, 128);
    const int tid = threadIdx.x, lane = tid & 31, wid = tid >> 5;
    const int wm = wid >> 1, wn = wid & 1;

    int* sTok = (int*)(smem + OFF_TOK);
    if (MODE == 1) {
        if (tid < 128) sTok[tid] = g_list[e * NTOK + m0 + min(tid, rows - 1)];
        __syncthreads();
    }

    const __half* pA[4]; uint32_t aOfs[4];
#pragma unroll
    for (int i = 0; i < 4; i++) {
        int idx = tid + i * 128, r = idx >> 2, c = idx & 3;
        size_t rb;
        if (MODE == 1) rb = (size_t)sTok[r] * DD;
        else           rb = ((size_t)e * NTOK + m0 + r) * FF;
        pA[i] = ((MODE == 1) ? g_Xh : g_H) + rb + c * 8;
        aOfs[i] = (uint32_t)(r * 80 + c * 16);
    }
    const __half* pB[4]; uint32_t bOfs[4];
#pragma unroll
    for (int i = 0; i < 4; i++) {
        int idx = tid + i * 128, k = idx >> 4, c = idx & 15;
        pB[i] = Bh + (size_t)e * KTOT * LDB + (size_t)k * LDB + n0 + c * 8;
        bOfs[i] = (uint32_t)(k * 272 + c * 16);
    }

    uint32_t aFrag[4];
#pragma unroll
    for (int ms = 0; ms < 4; ms++) {
        int row = wm * 64 + ms * 16 + (lane & 7) + ((lane >> 3) & 1) * 8;
        aFrag[ms] = (uint32_t)(row * 80 + ((lane >> 4) & 1) * 16);
    }
    uint32_t bFrag[4];
#pragma unroll
    for (int p = 0; p < 4; p++) {
        int k = (lane & 7) + ((lane >> 3) & 1) * 8;
        int n = wn * 64 + p * 16 + ((lane >> 4) & 1) * 8;
        bFrag[p] = (uint32_t)(k * 272 + n * 2);
    }

    float acc[4][8][4];
#pragma unroll
    for (int a = 0; a < 4; a++)
#pragma unroll
        for (int b = 0; b < 8; b++)
#pragma unroll
            for (int r = 0; r < 4; r++) acc[a][b][r] = 0.f;

    auto fill = [&](int kt) {
        int st = kt & 3;
        uint32_t sa = sbase + st * SA_ST;
        uint32_t sb = sbase + OFF_B + st * SB_ST;
#pragma unroll
        for (int i = 0; i < 4; i++)
            CP16(sa + aOfs[i], pA[i] + (size_t)kt * BK);
#pragma unroll
        for (int i = 0; i < 4; i++)
            CP16(sb + bOfs[i], pB[i] + (size_t)kt * BK * LDB);
    };

    uint32_t af[2][4][4], bf[2][8][2];
    auto loadSlab = [&](uint32_t sa, uint32_t sb, int s, int buf) {
#pragma unroll
        for (int ms = 0; ms < 4; ms++) {
            uint32_t addr = sa + aFrag[ms] + s * 32;
            asm volatile(
                "ldmatrix.sync.aligned.m8n8.x4.shared.b16 {%0,%1,%2,%3}, [%4];"
                : "=r"(af[buf][ms][0]), "=r"(af[buf][ms][1]),
                  "=r"(af[buf][ms][2]), "=r"(af[buf][ms][3]) : "r"(addr));
        }
#pragma unroll
        for (int p = 0; p < 4; p++) {
            uint32_t addr = sb + bFrag[p] + s * (16 * 272);
            asm volatile(
                "ldmatrix.sync.aligned.m8n8.x4.trans.shared.b16 {%0,%1,%2,%3}, [%4];"
                : "=r"(bf[buf][2 * p][0]), "=r"(bf[buf][2 * p][1]),
                  "=r"(bf[buf][2 * p + 1][0]), "=r"(bf[buf][2 * p + 1][1]) : "r"(addr));
        }
    };
    auto mmaSlab = [&](int buf) {
#pragma unroll
        for (int ms = 0; ms < 4; ms++)
#pragma unroll
            for (int ns = 0; ns < 8; ns++)
                mma16(acc[ms][ns], af[buf][ms], bf[buf][ns]);
    };

    fill(0); CP_COMMIT();
    fill(1); CP_COMMIT();
    fill(2); CP_COMMIT();
    for (int kt = 0; kt < KIT; kt++) {
        int st = kt & 3;
        uint32_t sa = sbase + st * SA_ST;
        uint32_t sb = sbase + OFF_B + st * SB_ST;
        CP_WAIT2();
        __syncthreads();
        loadSlab(sa, sb, 0, 0);          // slab0 LDSM latency hides under fill issue
        if (kt + 3 < KIT) fill(kt + 3);
        CP_COMMIT();
        loadSlab(sa, sb, 1, 1);          // slab1 LDSM latency hides under slab0 MMAs
        mmaSlab(0);
        mmaSlab(1);
    }

    constexpr int ND = (MODE == 1) ? FF : DD;
    const int lr = lane >> 2, lc = lane & 3;
#pragma unroll
    for (int ms = 0; ms < 4; ms++) {
#pragma unroll
        for (int half = 0; half < 2; half++) {
            int r = wm * 64 + ms * 16 + lr + half * 8;
            if (r >= rows) continue;
            size_t rowb = ((size_t)e * NTOK + m0 + r) * ND;
#pragma unroll
            for (int ns = 0; ns < 8; ns++) {
                int col = n0 + wn * 64 + ns * 8 + lc * 2;
                float2 bv = *(const float2*)&bias[(size_t)e * ND + col];
                float v0 = acc[ms][ns][half * 2 + 0] + bv.x;
                float v1 = acc[ms][ns][half * 2 + 1] + bv.y;
                if (MODE == 1) {
                    v0 = gelu(v0); v1 = gelu(v1);
                    *(__half2*)&g_H[rowb + col] =
                        __halves2half2(__float2half_rn(v0), __float2half_rn(v1));
                } else {
                    *(float2*)&g_Y[rowb + col] = make_float2(v0, v1);
                }
            }
        }
    }
}

// ---------------- combine + expert_counts + counter reset ----------------
__global__ void combine_kernel(float* __restrict__ out, float* __restrict__ counts) {
    int t = blockIdx.x;
    int i = threadIdx.x;
    if (t == 0 && i < NE) {
        if (counts) counts[i] = (float)g_cnt[i];
        g_cnt[i] = 0;
    }
    int p0 = g_cp[t * 2], p1 = g_cp[t * 2 + 1];
    float w0 = g_cw[t * 2], w1 = g_cw[t * 2 + 1];
    const float4* y0 = (const float4*)(g_Y + (size_t)p0 * DD);
    const float4* y1 = (const float4*)(g_Y + (size_t)p1 * DD);
    float4 a = y0[i], b = y1[i], r;
    r.x = w0 * a.x + w1 * b.x;
    r.y = w0 * a.y + w1 * b.y;
    r.z = w0 * a.z + w1 * b.z;
    r.w = w0 * a.w + w1 * b.w;
    ((float4*)(out + (size_t)t * DD))[i] = r;
}

// ---------------- launch (R11 structure) ----------------
extern "C" void kernel_launch(void* const* d_in, const int* in_sizes, int n_in,
                              void* d_out, int out_size) {
    const float* x  = (const float*)d_in[0];
    const float* gw = (const float*)d_in[1];
    const float* gb = (const float*)d_in[2];
    const float* w1 = (const float*)d_in[3];
    const float* b1 = (const float*)d_in[4];
    const float* w2 = (const float*)d_in[5];
    const float* b2 = (const float*)d_in[6];
    float* out = (float*)d_out;

    const long long OUT0 = (long long)NTOK * DD;
    long long os = out_size;
    float* gl = nullptr; float* tk = nullptr; float* cn = nullptr;
    if (os >= OUT0 + (long long)NTOK * NE)
        gl = out + OUT0;
    if (os >= OUT0 + (long long)NTOK * NE + NTOK * 2)
        tk = out + OUT0 + (long long)NTOK * NE;
    if (os >= OUT0 + (long long)NTOK * NE + NTOK * 2 + NE)
        cn = out + OUT0 + (long long)NTOK * NE + NTOK * 2;

    static __half* w1h = nullptr; static __half* w2h = nullptr;
    static cudaStream_t s1;
    static cudaEvent_t evFork, evW1, evW2;
    static bool init_done = false;
    if (!init_done) {
        cudaGetSymbolAddress((void**)&w1h, g_W1h);
        cudaGetSymbolAddress((void**)&w2h, g_W2h);
        cudaStreamCreateWithFlags(&s1, cudaStreamNonBlocking);
        cudaEventCreateWithFlags(&evFork, cudaEventDisableTiming);
        cudaEventCreateWithFlags(&evW1, cudaEventDisableTiming);
        cudaEventCreateWithFlags(&evW2, cudaEventDisableTiming);
        const int SM_ = 76288;
        cudaFuncSetAttribute(moe_gemm<DD, FF, 1>,
                             cudaFuncAttributeMaxDynamicSharedMemorySize, SM_);
        cudaFuncSetAttribute(moe_gemm<FF, DD, 2>,
                             cudaFuncAttributeMaxDynamicSharedMemorySize, SM_);
        init_done = true;
    }
    const int SMEM = 76288;
    cudaStream_t s0 = 0;

    cudaEventRecord(evFork, s0);
    cudaStreamWaitEvent(s1, evFork, 0);

    f2h_kernel<<<8192, 256, 0, s1>>>(w1, w1h, NE * DD * FF / 4);
    cudaEventRecord(evW1, s1);
    f2h_kernel<<<8192, 256, 0, s1>>>(w2, w2h, NE * FF * DD / 4);
    cudaEventRecord(evW2, s1);

    gate_kernel<<<NTOK, 256, 0, s0>>>(x, gw, gb, gl, tk);
    cudaStreamWaitEvent(s0, evW1, 0);
    moe_gemm<DD, FF, 1><<<dim3(FF / 128, NTOK / 128, NE), 128, SMEM, s0>>>(w1h, b1);
    cudaStreamWaitEvent(s0, evW2, 0);
    moe_gemm<FF, DD, 2><<<dim3(DD / 128, NTOK / 128, NE), 128, SMEM, s0>>>(w2h, b2);
    combine_kernel<<<NTOK, 256, 0, s0>>>(out, cn);
}

// round 15
// speedup vs baseline: 1.6306x; 1.0516x over previous
#include <cuda_runtime.h>
#include <cuda_fp16.h>
#include <math.h>
#include <stdint.h>

#define NTOK 4096   // B*T
#define DD   1024   // model dim
#define NE   8      // experts
#define FF   4096   // ffn dim

// ---------------- device scratch ----------------
__device__ int    g_cnt[NE];          // statically zero; combine re-zeros each run
__device__ int    g_list[NE * NTOK];
__device__ int    g_cp[NTOK * 2];
__device__ float  g_cw[NTOK * 2];
__device__ __half g_Xh[(size_t)NTOK * DD];
__device__ __half g_W1h[(size_t)NE * DD * FF];
__device__ __half g_W2h[(size_t)NE * FF * DD];
__device__ __half g_H[(size_t)NE * NTOK * FF];
__device__ float  g_Y[(size_t)NE * NTOK * DD];

// ---------------- fp32 -> fp16 conversion ----------------
__global__ void f2h_kernel(const float* __restrict__ src, __half* __restrict__ dst,
                           int n4) {
    int stride = gridDim.x * blockDim.x;
    for (int i = blockIdx.x * blockDim.x + threadIdx.x; i < n4; i += stride) {
        float4 v = ((const float4*)src)[i];
        __half2 h0 = __halves2half2(__float2half_rn(v.x), __float2half_rn(v.y));
        __half2 h1 = __halves2half2(__float2half_rn(v.z), __float2half_rn(v.w));
        uint2 u;
        u.x = *(uint32_t*)&h0;
        u.y = *(uint32_t*)&h1;
        ((uint2*)dst)[i] = u;
    }
}

// ---------------- gating (fp32 top-k) + fused x fp16 conversion ----------------
__global__ void gate_kernel(const float* __restrict__ x,
                            const float* __restrict__ gw,
                            const float* __restrict__ gb,
                            float* gate_logits, float* topk) {
    __shared__ float xs[DD];
    __shared__ float lg[NE];
    int t = blockIdx.x;
    const float4* xr = (const float4*)(x + (size_t)t * DD);
    for (int i = threadIdx.x; i < DD / 4; i += blockDim.x)
        ((float4*)xs)[i] = xr[i];
    __syncthreads();

    {
        int i = threadIdx.x;              // 256 threads == DD/4 chunks
        float4 v = ((const float4*)xs)[i];
        __half2 h0 = __halves2half2(__float2half_rn(v.x), __float2half_rn(v.y));
        __half2 h1 = __halves2half2(__float2half_rn(v.z), __float2half_rn(v.w));
        uint2 u;
        u.x = *(uint32_t*)&h0;
        u.y = *(uint32_t*)&h1;
        ((uint2*)(g_Xh + (size_t)t * DD))[i] = u;
    }

    int w = threadIdx.x >> 5, lane = threadIdx.x & 31;
    float s = 0.f;
    for (int j = lane; j < DD; j += 32) s += xs[j] * gw[j * NE + w];
#pragma unroll
    for (int o = 16; o; o >>= 1) s += __shfl_xor_sync(0xffffffffu, s, o);
    if (lane == 0) lg[w] = s + gb[w];
    __syncthreads();

    if (threadIdx.x == 0) {
        float v[NE];
#pragma unroll
        for (int e = 0; e < NE; e++) v[e] = lg[e];
        int i0 = 0;
        for (int e = 1; e < NE; e++) if (v[e] > v[i0]) i0 = e;
        int i1 = -1;
        for (int e = 0; e < NE; e++) {
            if (e == i0) continue;
            if (i1 < 0 || v[e] > v[i1]) i1 = e;
        }
        float ew = expf(v[i1] - v[i0]);
        float w0 = 1.f / (1.f + ew);
        float w1 = ew / (1.f + ew);

        int p0 = atomicAdd(&g_cnt[i0], 1);
        g_list[i0 * NTOK + p0] = t;
        int p1 = atomicAdd(&g_cnt[i1], 1);
        g_list[i1 * NTOK + p1] = t;
        g_cp[t * 2] = i0 * NTOK + p0;  g_cw[t * 2] = w0;
        g_cp[t * 2 + 1] = i1 * NTOK + p1;  g_cw[t * 2 + 1] = w1;

        if (gate_logits)
            for (int e = 0; e < NE; e++) gate_logits[(size_t)t * NE + e] = v[e];
        if (topk) { topk[t * 2] = (float)i0; topk[t * 2 + 1] = (float)i1; }
    }
}

// ---------------- helpers ----------------
__device__ __forceinline__ uint32_t smem_u32(const void* p) {
    uint32_t a;
    asm("{ .reg .u64 t; cvta.to.shared.u64 t, %1; cvt.u32.u64 %0, t; }"
        : "=r"(a) : "l"(p));
    return a;
}
__device__ __forceinline__ void mma16(float* c, const uint32_t* a, const uint32_t* b) {
    asm volatile(
        "mma.sync.aligned.m16n8k16.row.col.f32.f16.f16.f32 "
        "{%0,%1,%2,%3}, {%4,%5,%6,%7}, {%8,%9}, {%0,%1,%2,%3};"
        : "+f"(c[0]), "+f"(c[1]), "+f"(c[2]), "+f"(c[3])
        : "r"(a[0]), "r"(a[1]), "r"(a[2]), "r"(a[3]), "r"(b[0]), "r"(b[1]));
}
__device__ __forceinline__ float gelu(float v) {
    return 0.5f * v * (1.f + erff(v * 0.70710678118654752f));
}
#define CP16(dst, src) \
    asm volatile("cp.async.cg.shared.global [%0], [%1], 16;" :: "r"(dst), "l"(src))
#define CP_COMMIT() asm volatile("cp.async.commit_group;" ::: "memory")
#define CP_WAIT2() asm volatile("cp.async.wait_group 2;" ::: "memory")

// ---------------- fp16 sparse per-expert GEMM, cp.async + ldmatrix ----------------
// EXACT R11 (504us) device code; expert index = ebase + blockIdx.z.
// block 128x128, 128 threads, 2x2 warps (64x64 warp tile), BK=32, 4-stage cp.async
// MODE 1: A = gathered g_Xh rows -> gelu -> g_H (fp16)
// MODE 2: A = g_H rows -> +bias -> g_Y (fp32)
template <int KTOT, int LDB, int MODE>
__global__ void __launch_bounds__(128, 2)
moe_gemm(const __half* __restrict__ Bh, const float* __restrict__ bias, int ebase) {
    constexpr int BK = 32;
    constexpr int KIT = KTOT / BK;
    constexpr int SA_ST = 10240, SB_ST = 8704;
    constexpr int OFF_B = 4 * SA_ST;            // 40960
    constexpr int OFF_TOK = OFF_B + 4 * SB_ST;  // 75776
    extern __shared__ __align__(16) char smem[];
    const uint32_t sbase = smem_u32(smem);

    const int e = ebase + blockIdx.z;
    const int cnt = g_cnt[e];
    const int m0 = blockIdx.y * 128;
    if (m0 >= cnt) return;
    const int n0 = blockIdx.x * 128;
    const int rows = min(cnt - m0, 128);
    const int tid = threadIdx.x, lane = tid & 31, wid = tid >> 5;
    const int wm = wid >> 1, wn = wid & 1;

    int* sTok = (int*)(smem + OFF_TOK);
    if (MODE == 1) {
        if (tid < 128) sTok[tid] = g_list[e * NTOK + m0 + min(tid, rows - 1)];
        __syncthreads();
    }

    const __half* pA[4]; uint32_t aOfs[4];
#pragma unroll
    for (int i = 0; i < 4; i++) {
        int idx = tid + i * 128, r = idx >> 2, c = idx & 3;
        size_t rb;
        if (MODE == 1) rb = (size_t)sTok[r] * DD;
        else           rb = ((size_t)e * NTOK + m0 + r) * FF;
        pA[i] = ((MODE == 1) ? g_Xh : g_H) + rb + c * 8;
        aOfs[i] = (uint32_t)(r * 80 + c * 16);
    }
    const __half* pB[4]; uint32_t bOfs[4];
#pragma unroll
    for (int i = 0; i < 4; i++) {
        int idx = tid + i * 128, k = idx >> 4, c = idx & 15;
        pB[i] = Bh + (size_t)e * KTOT * LDB + (size_t)k * LDB + n0 + c * 8;
        bOfs[i] = (uint32_t)(k * 272 + c * 16);
    }

    uint32_t aFrag[4];
#pragma unroll
    for (int ms = 0; ms < 4; ms++) {
        int row = wm * 64 + ms * 16 + (lane & 7) + ((lane >> 3) & 1) * 8;
        aFrag[ms] = (uint32_t)(row * 80 + ((lane >> 4) & 1) * 16);
    }
    uint32_t bFrag[4];
#pragma unroll
    for (int p = 0; p < 4; p++) {
        int k = (lane & 7) + ((lane >> 3) & 1) * 8;
        int n = wn * 64 + p * 16 + ((lane >> 4) & 1) * 8;
        bFrag[p] = (uint32_t)(k * 272 + n * 2);
    }

    float acc[4][8][4];
#pragma unroll
    for (int a = 0; a < 4; a++)
#pragma unroll
        for (int b = 0; b < 8; b++)
#pragma unroll
            for (int r = 0; r < 4; r++) acc[a][b][r] = 0.f;

    auto fill = [&](int kt) {
        int st = kt & 3;
        uint32_t sa = sbase + st * SA_ST;
        uint32_t sb = sbase + OFF_B + st * SB_ST;
#pragma unroll
        for (int i = 0; i < 4; i++)
            CP16(sa + aOfs[i], pA[i] + (size_t)kt * BK);
#pragma unroll
        for (int i = 0; i < 4; i++)
            CP16(sb + bOfs[i], pB[i] + (size_t)kt * BK * LDB);
    };
    auto compute = [&](int kt) {
        int st = kt & 3;
        uint32_t sa = sbase + st * SA_ST;
        uint32_t sb = sbase + OFF_B + st * SB_ST;
#pragma unroll
        for (int s = 0; s < 2; s++) {
            uint32_t af[4][4], bf[8][2];
#pragma unroll
            for (int ms = 0; ms < 4; ms++) {
                uint32_t addr = sa + aFrag[ms] + s * 32;
                asm volatile(
                    "ldmatrix.sync.aligned.m8n8.x4.shared.b16 {%0,%1,%2,%3}, [%4];"
                    : "=r"(af[ms][0]), "=r"(af[ms][1]),
                      "=r"(af[ms][2]), "=r"(af[ms][3]) : "r"(addr));
            }
#pragma unroll
            for (int p = 0; p < 4; p++) {
                uint32_t addr = sb + bFrag[p] + s * (16 * 272);
                asm volatile(
                    "ldmatrix.sync.aligned.m8n8.x4.trans.shared.b16 {%0,%1,%2,%3}, [%4];"
                    : "=r"(bf[2 * p][0]), "=r"(bf[2 * p][1]),
                      "=r"(bf[2 * p + 1][0]), "=r"(bf[2 * p + 1][1]) : "r"(addr));
            }
#pragma unroll
            for (int ms = 0; ms < 4; ms++)
#pragma unroll
                for (int ns = 0; ns < 8; ns++)
                    mma16(acc[ms][ns], af[ms], bf[ns]);
        }
    };

    fill(0); CP_COMMIT();
    fill(1); CP_COMMIT();
    fill(2); CP_COMMIT();
    for (int kt = 0; kt < KIT; kt++) {
        CP_WAIT2();
        __syncthreads();
        if (kt + 3 < KIT) fill(kt + 3);
        CP_COMMIT();
        compute(kt);
    }

    constexpr int ND = (MODE == 1) ? FF : DD;
    const int lr = lane >> 2, lc = lane & 3;
#pragma unroll
    for (int ms = 0; ms < 4; ms++) {
#pragma unroll
        for (int half = 0; half < 2; half++) {
            int r = wm * 64 + ms * 16 + lr + half * 8;
            if (r >= rows) continue;
            size_t rowb = ((size_t)e * NTOK + m0 + r) * ND;
#pragma unroll
            for (int ns = 0; ns < 8; ns++) {
                int col = n0 + wn * 64 + ns * 8 + lc * 2;
                float2 bv = *(const float2*)&bias[(size_t)e * ND + col];
                float v0 = acc[ms][ns][half * 2 + 0] + bv.x;
                float v1 = acc[ms][ns][half * 2 + 1] + bv.y;
                if (MODE == 1) {
                    v0 = gelu(v0); v1 = gelu(v1);
                    *(__half2*)&g_H[rowb + col] =
                        __halves2half2(__float2half_rn(v0), __float2half_rn(v1));
                } else {
                    *(float2*)&g_Y[rowb + col] = make_float2(v0, v1);
                }
            }
        }
    }
}

// ---------------- combine + expert_counts + counter reset ----------------
__global__ void combine_kernel(float* __restrict__ out, float* __restrict__ counts) {
    int t = blockIdx.x;
    int i = threadIdx.x;
    if (t == 0 && i < NE) {
        if (counts) counts[i] = (float)g_cnt[i];
        g_cnt[i] = 0;
    }
    int p0 = g_cp[t * 2], p1 = g_cp[t * 2 + 1];
    float w0 = g_cw[t * 2], w1 = g_cw[t * 2 + 1];
    const float4* y0 = (const float4*)(g_Y + (size_t)p0 * DD);
    const float4* y1 = (const float4*)(g_Y + (size_t)p1 * DD);
    float4 a = y0[i], b = y1[i], r;
    r.x = w0 * a.x + w1 * b.x;
    r.y = w0 * a.y + w1 * b.y;
    r.z = w0 * a.z + w1 * b.z;
    r.w = w0 * a.w + w1 * b.w;
    ((float4*)(out + (size_t)t * DD))[i] = r;
}

// ---------------- launch: half-split GEMMs, pipelined across 2 chains ----------
extern "C" void kernel_launch(void* const* d_in, const int* in_sizes, int n_in,
                              void* d_out, int out_size) {
    const float* x  = (const float*)d_in[0];
    const float* gw = (const float*)d_in[1];
    const float* gb = (const float*)d_in[2];
    const float* w1 = (const float*)d_in[3];
    const float* b1 = (const float*)d_in[4];
    const float* w2 = (const float*)d_in[5];
    const float* b2 = (const float*)d_in[6];
    float* out = (float*)d_out;

    const long long OUT0 = (long long)NTOK * DD;
    long long os = out_size;
    float* gl = nullptr; float* tk = nullptr; float* cn = nullptr;
    if (os >= OUT0 + (long long)NTOK * NE)
        gl = out + OUT0;
    if (os >= OUT0 + (long long)NTOK * NE + NTOK * 2)
        tk = out + OUT0 + (long long)NTOK * NE;
    if (os >= OUT0 + (long long)NTOK * NE + NTOK * 2 + NE)
        cn = out + OUT0 + (long long)NTOK * NE + NTOK * 2;

    static __half* w1h = nullptr; static __half* w2h = nullptr;
    static cudaStream_t s1, s2;
    static cudaEvent_t evFork, evW1a, evW1b, evW2, ev1a, ev1b, ev2;
    static bool init_done = false;
    if (!init_done) {
        cudaGetSymbolAddress((void**)&w1h, g_W1h);
        cudaGetSymbolAddress((void**)&w2h, g_W2h);
        cudaStreamCreateWithFlags(&s1, cudaStreamNonBlocking);
        cudaStreamCreateWithFlags(&s2, cudaStreamNonBlocking);
        cudaEventCreateWithFlags(&evFork, cudaEventDisableTiming);
        cudaEventCreateWithFlags(&evW1a, cudaEventDisableTiming);
        cudaEventCreateWithFlags(&evW1b, cudaEventDisableTiming);
        cudaEventCreateWithFlags(&evW2, cudaEventDisableTiming);
        cudaEventCreateWithFlags(&ev1a, cudaEventDisableTiming);
        cudaEventCreateWithFlags(&ev1b, cudaEventDisableTiming);
        cudaEventCreateWithFlags(&ev2, cudaEventDisableTiming);
        const int SM_ = 76288;
        cudaFuncSetAttribute(moe_gemm<DD, FF, 1>,
                             cudaFuncAttributeMaxDynamicSharedMemorySize, SM_);
        cudaFuncSetAttribute(moe_gemm<FF, DD, 2>,
                             cudaFuncAttributeMaxDynamicSharedMemorySize, SM_);
        init_done = true;
    }
    const int SMEM = 76288;
    cudaStream_t s0 = 0;

    const long long W1HALF = (long long)(NE / 2) * DD * FF;   // 16M elements
    const dim3 G1(FF / 128, NTOK / 128, NE / 2);
    const dim3 G2(DD / 128, NTOK / 128, NE / 2);

    cudaEventRecord(evFork, s0);
    cudaStreamWaitEvent(s1, evFork, 0);
    cudaStreamWaitEvent(s2, evFork, 0);

    // s1: conversions — w1 in two halves so GEMM1a can start early
    f2h_kernel<<<4096, 256, 0, s1>>>(w1, w1h, (int)(W1HALF / 4));
    cudaEventRecord(evW1a, s1);
    f2h_kernel<<<4096, 256, 0, s1>>>(w1 + W1HALF, w1h + W1HALF, (int)(W1HALF / 4));
    cudaEventRecord(evW1b, s1);
    f2h_kernel<<<8192, 256, 0, s1>>>(w2, w2h, NE * FF * DD / 4);
    cudaEventRecord(evW2, s1);

    // s0: gate, then GEMM1 halves
    gate_kernel<<<NTOK, 256, 0, s0>>>(x, gw, gb, gl, tk);
    cudaStreamWaitEvent(s0, evW1a, 0);
    moe_gemm<DD, FF, 1><<<G1, 128, SMEM, s0>>>(w1h, b1, 0);
    cudaEventRecord(ev1a, s0);
    cudaStreamWaitEvent(s0, evW1b, 0);
    moe_gemm<DD, FF, 1><<<G1, 128, SMEM, s0>>>(w1h, b1, NE / 2);
    cudaEventRecord(ev1b, s0);

    // s2: GEMM2 halves — first half overlaps GEMM1's second half
    cudaStreamWaitEvent(s2, evW2, 0);
    cudaStreamWaitEvent(s2, ev1a, 0);
    moe_gemm<FF, DD, 2><<<G2, 128, SMEM, s2>>>(w2h, b2, 0);
    cudaStreamWaitEvent(s2, ev1b, 0);
    moe_gemm<FF, DD, 2><<<G2, 128, SMEM, s2>>>(w2h, b2, NE / 2);
    cudaEventRecord(ev2, s2);

    // join for combine
    cudaStreamWaitEvent(s0, ev2, 0);
    combine_kernel<<<NTOK, 256, 0, s0>>>(out, cn);
}

// round 16
// speedup vs baseline: 1.6574x; 1.0165x over previous
#include <cuda_runtime.h>
#include <cuda_fp16.h>
#include <math.h>
#include <stdint.h>

#define NTOK 4096   // B*T
#define DD   1024   // model dim
#define NE   8      // experts
#define FF   4096   // ffn dim

// ---------------- device scratch ----------------
__device__ int    g_cnt[NE];          // statically zero; combine re-zeros each run
__device__ int    g_list[NE * NTOK];
__device__ int    g_cp[NTOK * 2];
__device__ float  g_cw[NTOK * 2];
__device__ __half g_Xh[(size_t)NTOK * DD];
__device__ __half g_W1h[(size_t)NE * DD * FF];
__device__ __half g_W2h[(size_t)NE * FF * DD];
__device__ __half g_H[(size_t)NE * NTOK * FF];
__device__ float  g_Y[(size_t)NE * NTOK * DD];

// ---------------- fp32 -> fp16 conversion ----------------
__global__ void f2h_kernel(const float* __restrict__ src, __half* __restrict__ dst,
                           int n4) {
    int stride = gridDim.x * blockDim.x;
    for (int i = blockIdx.x * blockDim.x + threadIdx.x; i < n4; i += stride) {
        float4 v = ((const float4*)src)[i];
        __half2 h0 = __halves2half2(__float2half_rn(v.x), __float2half_rn(v.y));
        __half2 h1 = __halves2half2(__float2half_rn(v.z), __float2half_rn(v.w));
        uint2 u;
        u.x = *(uint32_t*)&h0;
        u.y = *(uint32_t*)&h1;
        ((uint2*)dst)[i] = u;
    }
}

// ---------------- gating: coalesced per-thread GEMV + fused x f2h ----------------
__global__ void gate_kernel(const float* __restrict__ x,
                            const float* __restrict__ gw,
                            const float* __restrict__ gb,
                            float* gate_logits, float* topk) {
    __shared__ float red[8][NE];       // per-warp partial sums
    __shared__ float lg[NE];
    int t = blockIdx.x;
    int tid = threadIdx.x, lane = tid & 31, wrp = tid >> 5;

    // thread tid owns x chunk [4*tid, 4*tid+4)
    float4 v = ((const float4*)(x + (size_t)t * DD))[tid];

    // fused fp16 copy of x row
    {
        __half2 h0 = __halves2half2(__float2half_rn(v.x), __float2half_rn(v.y));
        __half2 h1 = __halves2half2(__float2half_rn(v.z), __float2half_rn(v.w));
        uint2 u;
        u.x = *(uint32_t*)&h0;
        u.y = *(uint32_t*)&h1;
        ((uint2*)(g_Xh + (size_t)t * DD))[tid] = u;
    }

    // partial logits: gw rows 4*tid .. 4*tid+3 (contiguous 128B per thread)
    float acc[NE];
    const float xv[4] = {v.x, v.y, v.z, v.w};
#pragma unroll
    for (int e = 0; e < NE; e++) acc[e] = 0.f;
#pragma unroll
    for (int j = 0; j < 4; j++) {
        const float4* gr = (const float4*)(gw + (size_t)(4 * tid + j) * NE);
        float4 g0 = gr[0], g1 = gr[1];
        acc[0] += xv[j] * g0.x;  acc[1] += xv[j] * g0.y;
        acc[2] += xv[j] * g0.z;  acc[3] += xv[j] * g0.w;
        acc[4] += xv[j] * g1.x;  acc[5] += xv[j] * g1.y;
        acc[6] += xv[j] * g1.z;  acc[7] += xv[j] * g1.w;
    }
    // warp reduce each accumulator
#pragma unroll
    for (int e = 0; e < NE; e++) {
#pragma unroll
        for (int o = 16; o; o >>= 1)
            acc[e] += __shfl_xor_sync(0xffffffffu, acc[e], o);
    }
    if (lane == 0)
#pragma unroll
        for (int e = 0; e < NE; e++) red[wrp][e] = acc[e];
    __syncthreads();
    if (tid < NE) {
        float s = gb[tid];
#pragma unroll
        for (int w = 0; w < 8; w++) s += red[w][tid];
        lg[tid] = s;
    }
    __syncthreads();

    if (tid == 0) {
        float v8[NE];
#pragma unroll
        for (int e = 0; e < NE; e++) v8[e] = lg[e];
        int i0 = 0;
        for (int e = 1; e < NE; e++) if (v8[e] > v8[i0]) i0 = e;   // stable argmax
        int i1 = -1;
        for (int e = 0; e < NE; e++) {
            if (e == i0) continue;
            if (i1 < 0 || v8[e] > v8[i1]) i1 = e;                  // stable second
        }
        float ew = expf(v8[i1] - v8[i0]);
        float w0 = 1.f / (1.f + ew);
        float w1 = ew / (1.f + ew);

        int p0 = atomicAdd(&g_cnt[i0], 1);
        g_list[i0 * NTOK + p0] = t;
        int p1 = atomicAdd(&g_cnt[i1], 1);
        g_list[i1 * NTOK + p1] = t;
        g_cp[t * 2] = i0 * NTOK + p0;  g_cw[t * 2] = w0;
        g_cp[t * 2 + 1] = i1 * NTOK + p1;  g_cw[t * 2 + 1] = w1;

        if (gate_logits)
            for (int e = 0; e < NE; e++) gate_logits[(size_t)t * NE + e] = v8[e];
        if (topk) { topk[t * 2] = (float)i0; topk[t * 2 + 1] = (float)i1; }
    }
}

// ---------------- helpers ----------------
__device__ __forceinline__ uint32_t smem_u32(const void* p) {
    uint32_t a;
    asm("{ .reg .u64 t; cvta.to.shared.u64 t, %1; cvt.u32.u64 %0, t; }"
        : "=r"(a) : "l"(p));
    return a;
}
__device__ __forceinline__ void mma16(float* c, const uint32_t* a, const uint32_t* b) {
    asm volatile(
        "mma.sync.aligned.m16n8k16.row.col.f32.f16.f16.f32 "
        "{%0,%1,%2,%3}, {%4,%5,%6,%7}, {%8,%9}, {%0,%1,%2,%3};"
        : "+f"(c[0]), "+f"(c[1]), "+f"(c[2]), "+f"(c[3])
        : "r"(a[0]), "r"(a[1]), "r"(a[2]), "r"(a[3]), "r"(b[0]), "r"(b[1]));
}
__device__ __forceinline__ float gelu(float v) {
    return 0.5f * v * (1.f + erff(v * 0.70710678118654752f));
}
#define CP16(dst, src) \
    asm volatile("cp.async.cg.shared.global [%0], [%1], 16;" :: "r"(dst), "l"(src))
#define CP_COMMIT() asm volatile("cp.async.commit_group;" ::: "memory")
#define CP_WAIT2() asm volatile("cp.async.wait_group 2;" ::: "memory")

// ---------------- fp16 sparse per-expert GEMM, cp.async + ldmatrix ----------------
// EXACT R11 (504us) device code; expert index = ebase + blockIdx.z.
// block 128x128, 128 threads, 2x2 warps (64x64 warp tile), BK=32, 4-stage cp.async
// MODE 1: A = gathered g_Xh rows -> gelu -> g_H (fp16)
// MODE 2: A = g_H rows -> +bias -> g_Y (fp32)
template <int KTOT, int LDB, int MODE>
__global__ void __launch_bounds__(128, 2)
moe_gemm(const __half* __restrict__ Bh, const float* __restrict__ bias, int ebase) {
    constexpr int BK = 32;
    constexpr int KIT = KTOT / BK;
    constexpr int SA_ST = 10240, SB_ST = 8704;
    constexpr int OFF_B = 4 * SA_ST;            // 40960
    constexpr int OFF_TOK = OFF_B + 4 * SB_ST;  // 75776
    extern __shared__ __align__(16) char smem[];
    const uint32_t sbase = smem_u32(smem);

    const int e = ebase + blockIdx.z;
    const int cnt = g_cnt[e];
    const int m0 = blockIdx.y * 128;
    if (m0 >= cnt) return;
    const int n0 = blockIdx.x * 128;
    const int rows = min(cnt - m0, 128);
    const int tid = threadIdx.x, lane = tid & 31, wid = tid >> 5;
    const int wm = wid >> 1, wn = wid & 1;

    int* sTok = (int*)(smem + OFF_TOK);
    if (MODE == 1) {
        if (tid < 128) sTok[tid] = g_list[e * NTOK + m0 + min(tid, rows - 1)];
        __syncthreads();
    }

    const __half* pA[4]; uint32_t aOfs[4];
#pragma unroll
    for (int i = 0; i < 4; i++) {
        int idx = tid + i * 128, r = idx >> 2, c = idx & 3;
        size_t rb;
        if (MODE == 1) rb = (size_t)sTok[r] * DD;
        else           rb = ((size_t)e * NTOK + m0 + r) * FF;
        pA[i] = ((MODE == 1) ? g_Xh : g_H) + rb + c * 8;
        aOfs[i] = (uint32_t)(r * 80 + c * 16);
    }
    const __half* pB[4]; uint32_t bOfs[4];
#pragma unroll
    for (int i = 0; i < 4; i++) {
        int idx = tid + i * 128, k = idx >> 4, c = idx & 15;
        pB[i] = Bh + (size_t)e * KTOT * LDB + (size_t)k * LDB + n0 + c * 8;
        bOfs[i] = (uint32_t)(k * 272 + c * 16);
    }

    uint32_t aFrag[4];
#pragma unroll
    for (int ms = 0; ms < 4; ms++) {
        int row = wm * 64 + ms * 16 + (lane & 7) + ((lane >> 3) & 1) * 8;
        aFrag[ms] = (uint32_t)(row * 80 + ((lane >> 4) & 1) * 16);
    }
    uint32_t bFrag[4];
#pragma unroll
    for (int p = 0; p < 4; p++) {
        int k = (lane & 7) + ((lane >> 3) & 1) * 8;
        int n = wn * 64 + p * 16 + ((lane >> 4) & 1) * 8;
        bFrag[p] = (uint32_t)(k * 272 + n * 2);
    }

    float acc[4][8][4];
#pragma unroll
    for (int a = 0; a < 4; a++)
#pragma unroll
        for (int b = 0; b < 8; b++)
#pragma unroll
            for (int r = 0; r < 4; r++) acc[a][b][r] = 0.f;

    auto fill = [&](int kt) {
        int st = kt & 3;
        uint32_t sa = sbase + st * SA_ST;
        uint32_t sb = sbase + OFF_B + st * SB_ST;
#pragma unroll
        for (int i = 0; i < 4; i++)
            CP16(sa + aOfs[i], pA[i] + (size_t)kt * BK);
#pragma unroll
        for (int i = 0; i < 4; i++)
            CP16(sb + bOfs[i], pB[i] + (size_t)kt * BK * LDB);
    };
    auto compute = [&](int kt) {
        int st = kt & 3;
        uint32_t sa = sbase + st * SA_ST;
        uint32_t sb = sbase + OFF_B + st * SB_ST;
#pragma unroll
        for (int s = 0; s < 2; s++) {
            uint32_t af[4][4], bf[8][2];
#pragma unroll
            for (int ms = 0; ms < 4; ms++) {
                uint32_t addr = sa + aFrag[ms] + s * 32;
                asm volatile(
                    "ldmatrix.sync.aligned.m8n8.x4.shared.b16 {%0,%1,%2,%3}, [%4];"
                    : "=r"(af[ms][0]), "=r"(af[ms][1]),
                      "=r"(af[ms][2]), "=r"(af[ms][3]) : "r"(addr));
            }
#pragma unroll
            for (int p = 0; p < 4; p++) {
                uint32_t addr = sb + bFrag[p] + s * (16 * 272);
                asm volatile(
                    "ldmatrix.sync.aligned.m8n8.x4.trans.shared.b16 {%0,%1,%2,%3}, [%4];"
                    : "=r"(bf[2 * p][0]), "=r"(bf[2 * p][1]),
                      "=r"(bf[2 * p + 1][0]), "=r"(bf[2 * p + 1][1]) : "r"(addr));
            }
#pragma unroll
            for (int ms = 0; ms < 4; ms++)
#pragma unroll
                for (int ns = 0; ns < 8; ns++)
                    mma16(acc[ms][ns], af[ms], bf[ns]);
        }
    };

    fill(0); CP_COMMIT();
    fill(1); CP_COMMIT();
    fill(2); CP_COMMIT();
    for (int kt = 0; kt < KIT; kt++) {
        CP_WAIT2();
        __syncthreads();
        if (kt + 3 < KIT) fill(kt + 3);
        CP_COMMIT();
        compute(kt);
    }

    constexpr int ND = (MODE == 1) ? FF : DD;
    const int lr = lane >> 2, lc = lane & 3;
#pragma unroll
    for (int ms = 0; ms < 4; ms++) {
#pragma unroll
        for (int half = 0; half < 2; half++) {
            int r = wm * 64 + ms * 16 + lr + half * 8;
            if (r >= rows) continue;
            size_t rowb = ((size_t)e * NTOK + m0 + r) * ND;
#pragma unroll
            for (int ns = 0; ns < 8; ns++) {
                int col = n0 + wn * 64 + ns * 8 + lc * 2;
                float2 bv = *(const float2*)&bias[(size_t)e * ND + col];
                float v0 = acc[ms][ns][half * 2 + 0] + bv.x;
                float v1 = acc[ms][ns][half * 2 + 1] + bv.y;
                if (MODE == 1) {
                    v0 = gelu(v0); v1 = gelu(v1);
                    *(__half2*)&g_H[rowb + col] =
                        __halves2half2(__float2half_rn(v0), __float2half_rn(v1));
                } else {
                    *(float2*)&g_Y[rowb + col] = make_float2(v0, v1);
                }
            }
        }
    }
}

// ---------------- combine + expert_counts + counter reset ----------------
__global__ void combine_kernel(float* __restrict__ out, float* __restrict__ counts) {
    int t = blockIdx.x;
    int i = threadIdx.x;
    if (t == 0 && i < NE) {
        if (counts) counts[i] = (float)g_cnt[i];
        g_cnt[i] = 0;
    }
    int p0 = g_cp[t * 2], p1 = g_cp[t * 2 + 1];
    float w0 = g_cw[t * 2], w1 = g_cw[t * 2 + 1];
    const float4* y0 = (const float4*)(g_Y + (size_t)p0 * DD);
    const float4* y1 = (const float4*)(g_Y + (size_t)p1 * DD);
    float4 a = y0[i], b = y1[i], r;
    r.x = w0 * a.x + w1 * b.x;
    r.y = w0 * a.y + w1 * b.y;
    r.z = w0 * a.z + w1 * b.z;
    r.w = w0 * a.w + w1 * b.w;
    ((float4*)(out + (size_t)t * DD))[i] = r;
}

// ---------------- launch: half-split GEMMs, pipelined across 2 chains ----------
extern "C" void kernel_launch(void* const* d_in, const int* in_sizes, int n_in,
                              void* d_out, int out_size) {
    const float* x  = (const float*)d_in[0];
    const float* gw = (const float*)d_in[1];
    const float* gb = (const float*)d_in[2];
    const float* w1 = (const float*)d_in[3];
    const float* b1 = (const float*)d_in[4];
    const float* w2 = (const float*)d_in[5];
    const float* b2 = (const float*)d_in[6];
    float* out = (float*)d_out;

    const long long OUT0 = (long long)NTOK * DD;
    long long os = out_size;
    float* gl = nullptr; float* tk = nullptr; float* cn = nullptr;
    if (os >= OUT0 + (long long)NTOK * NE)
        gl = out + OUT0;
    if (os >= OUT0 + (long long)NTOK * NE + NTOK * 2)
        tk = out + OUT0 + (long long)NTOK * NE;
    if (os >= OUT0 + (long long)NTOK * NE + NTOK * 2 + NE)
        cn = out + OUT0 + (long long)NTOK * NE + NTOK * 2;

    static __half* w1h = nullptr; static __half* w2h = nullptr;
    static cudaStream_t s1, s2;
    static cudaEvent_t evFork, evW1a, evW1b, evW2, ev1a, ev1b, ev2;
    static bool init_done = false;
    if (!init_done) {
        cudaGetSymbolAddress((void**)&w1h, g_W1h);
        cudaGetSymbolAddress((void**)&w2h, g_W2h);
        cudaStreamCreateWithFlags(&s1, cudaStreamNonBlocking);
        cudaStreamCreateWithFlags(&s2, cudaStreamNonBlocking);
        cudaEventCreateWithFlags(&evFork, cudaEventDisableTiming);
        cudaEventCreateWithFlags(&evW1a, cudaEventDisableTiming);
        cudaEventCreateWithFlags(&evW1b, cudaEventDisableTiming);
        cudaEventCreateWithFlags(&evW2, cudaEventDisableTiming);
        cudaEventCreateWithFlags(&ev1a, cudaEventDisableTiming);
        cudaEventCreateWithFlags(&ev1b, cudaEventDisableTiming);
        cudaEventCreateWithFlags(&ev2, cudaEventDisableTiming);
        const int SM_ = 76288;
        cudaFuncSetAttribute(moe_gemm<DD, FF, 1>,
                             cudaFuncAttributeMaxDynamicSharedMemorySize, SM_);
        cudaFuncSetAttribute(moe_gemm<FF, DD, 2>,
                             cudaFuncAttributeMaxDynamicSharedMemorySize, SM_);
        init_done = true;
    }
    const int SMEM = 76288;
    cudaStream_t s0 = 0;

    const long long W1HALF = (long long)(NE / 2) * DD * FF;   // 16M elements
    const dim3 G1(FF / 128, NTOK / 128, NE / 2);
    const dim3 G2(DD / 128, NTOK / 128, NE / 2);

    cudaEventRecord(evFork, s0);
    cudaStreamWaitEvent(s1, evFork, 0);
    cudaStreamWaitEvent(s2, evFork, 0);

    // s1: conversions — w1 in two halves so GEMM1a can start early
    f2h_kernel<<<4096, 256, 0, s1>>>(w1, w1h, (int)(W1HALF / 4));
    cudaEventRecord(evW1a, s1);
    f2h_kernel<<<4096, 256, 0, s1>>>(w1 + W1HALF, w1h + W1HALF, (int)(W1HALF / 4));
    cudaEventRecord(evW1b, s1);
    f2h_kernel<<<8192, 256, 0, s1>>>(w2, w2h, NE * FF * DD / 4);
    cudaEventRecord(evW2, s1);

    // s0: gate, then GEMM1 halves
    gate_kernel<<<NTOK, 256, 0, s0>>>(x, gw, gb, gl, tk);
    cudaStreamWaitEvent(s0, evW1a, 0);
    moe_gemm<DD, FF, 1><<<G1, 128, SMEM, s0>>>(w1h, b1, 0);
    cudaEventRecord(ev1a, s0);
    cudaStreamWaitEvent(s0, evW1b, 0);
    moe_gemm<DD, FF, 1><<<G1, 128, SMEM, s0>>>(w1h, b1, NE / 2);
    cudaEventRecord(ev1b, s0);

    // s2: GEMM2 halves — first half overlaps GEMM1's second half
    cudaStreamWaitEvent(s2, evW2, 0);
    cudaStreamWaitEvent(s2, ev1a, 0);
    moe_gemm<FF, DD, 2><<<G2, 128, SMEM, s2>>>(w2h, b2, 0);
    cudaStreamWaitEvent(s2, ev1b, 0);
    moe_gemm<FF, DD, 2><<<G2, 128, SMEM, s2>>>(w2h, b2, NE / 2);
    cudaEventRecord(ev2, s2);

    // join for combine
    cudaStreamWaitEvent(s0, ev2, 0);
    combine_kernel<<<NTOK, 256, 0, s0>>>(out, cn);
}

// round 17
// speedup vs baseline: 1.7128x; 1.0334x over previous
#include <cuda_runtime.h>
#include <cuda_fp16.h>
#include <math.h>
#include <stdint.h>

#define NTOK 4096   // B*T
#define DD   1024   // model dim
#define NE   8      // experts
#define FF   4096   // ffn dim

// ---------------- device scratch ----------------
__device__ int    g_cnt[NE];          // statically zero; combine re-zeros each run
__device__ int    g_list[NE * NTOK];
__device__ int    g_cp[NTOK * 2];
__device__ float  g_cw[NTOK * 2];
__device__ __half g_Xh[(size_t)NTOK * DD];
__device__ __half g_W1h[(size_t)NE * DD * FF];
__device__ __half g_W2h[(size_t)NE * FF * DD];
__device__ __half g_H[(size_t)NE * NTOK * FF];
__device__ float  g_Y[(size_t)NE * NTOK * DD];

// ---------------- fp32 -> fp16 conversion ----------------
__global__ void f2h_kernel(const float* __restrict__ src, __half* __restrict__ dst,
                           int n4) {
    int stride = gridDim.x * blockDim.x;
    for (int i = blockIdx.x * blockDim.x + threadIdx.x; i < n4; i += stride) {
        float4 v = ((const float4*)src)[i];
        __half2 h0 = __halves2half2(__float2half_rn(v.x), __float2half_rn(v.y));
        __half2 h1 = __halves2half2(__float2half_rn(v.z), __float2half_rn(v.w));
        uint2 u;
        u.x = *(uint32_t*)&h0;
        u.y = *(uint32_t*)&h1;
        ((uint2*)dst)[i] = u;
    }
}

// ---------------- gating: unit-row-stride GEMV + fused x f2h ----------------
// thread tid handles gw rows r = tid + 256*j  (lane stride = 1 row = 32B -> 4 lanes/line)
__global__ void gate_kernel(const float* __restrict__ x,
                            const float* __restrict__ gw,
                            const float* __restrict__ gb,
                            float* gate_logits, float* topk) {
    __shared__ float xs[DD];           // staged x row (bank-conflict-free scalar reads)
    __shared__ float red[8][NE];
    __shared__ float lg[NE];
    int t = blockIdx.x;
    int tid = threadIdx.x, lane = tid & 31, wrp = tid >> 5;

    // load x row (coalesced float4), stage to smem, write fp16 copy
    float4 v = ((const float4*)(x + (size_t)t * DD))[tid];
    ((float4*)xs)[tid] = v;
    {
        __half2 h0 = __halves2half2(__float2half_rn(v.x), __float2half_rn(v.y));
        __half2 h1 = __halves2half2(__float2half_rn(v.z), __float2half_rn(v.w));
        uint2 u;
        u.x = *(uint32_t*)&h0;
        u.y = *(uint32_t*)&h1;
        ((uint2*)(g_Xh + (size_t)t * DD))[tid] = u;
    }
    __syncthreads();

    float acc[NE];
#pragma unroll
    for (int e = 0; e < NE; e++) acc[e] = 0.f;
#pragma unroll
    for (int j = 0; j < 4; j++) {
        int r = tid + 256 * j;
        float xr = xs[r];                       // bank = tid mod 32, conflict-free
        const float4* gr = (const float4*)(gw + (size_t)r * NE);
        float4 g0 = gr[0], g1 = gr[1];          // 32B per lane, 4 lanes per 128B line
        acc[0] += xr * g0.x;  acc[1] += xr * g0.y;
        acc[2] += xr * g0.z;  acc[3] += xr * g0.w;
        acc[4] += xr * g1.x;  acc[5] += xr * g1.y;
        acc[6] += xr * g1.z;  acc[7] += xr * g1.w;
    }
#pragma unroll
    for (int e = 0; e < NE; e++) {
#pragma unroll
        for (int o = 16; o; o >>= 1)
            acc[e] += __shfl_xor_sync(0xffffffffu, acc[e], o);
    }
    if (lane == 0)
#pragma unroll
        for (int e = 0; e < NE; e++) red[wrp][e] = acc[e];
    __syncthreads();
    if (tid < NE) {
        float s = gb[tid];
#pragma unroll
        for (int w = 0; w < 8; w++) s += red[w][tid];
        lg[tid] = s;
    }
    __syncthreads();

    if (tid == 0) {
        float v8[NE];
#pragma unroll
        for (int e = 0; e < NE; e++) v8[e] = lg[e];
        int i0 = 0;
        for (int e = 1; e < NE; e++) if (v8[e] > v8[i0]) i0 = e;   // stable argmax
        int i1 = -1;
        for (int e = 0; e < NE; e++) {
            if (e == i0) continue;
            if (i1 < 0 || v8[e] > v8[i1]) i1 = e;                  // stable second
        }
        float ew = expf(v8[i1] - v8[i0]);
        float w0 = 1.f / (1.f + ew);
        float w1 = ew / (1.f + ew);

        int p0 = atomicAdd(&g_cnt[i0], 1);
        g_list[i0 * NTOK + p0] = t;
        int p1 = atomicAdd(&g_cnt[i1], 1);
        g_list[i1 * NTOK + p1] = t;
        g_cp[t * 2] = i0 * NTOK + p0;  g_cw[t * 2] = w0;
        g_cp[t * 2 + 1] = i1 * NTOK + p1;  g_cw[t * 2 + 1] = w1;

        if (gate_logits)
            for (int e = 0; e < NE; e++) gate_logits[(size_t)t * NE + e] = v8[e];
        if (topk) { topk[t * 2] = (float)i0; topk[t * 2 + 1] = (float)i1; }
    }
}

// ---------------- helpers ----------------
__device__ __forceinline__ uint32_t smem_u32(const void* p) {
    uint32_t a;
    asm("{ .reg .u64 t; cvta.to.shared.u64 t, %1; cvt.u32.u64 %0, t; }"
        : "=r"(a) : "l"(p));
    return a;
}
__device__ __forceinline__ void mma16(float* c, const uint32_t* a, const uint32_t* b) {
    asm volatile(
        "mma.sync.aligned.m16n8k16.row.col.f32.f16.f16.f32 "
        "{%0,%1,%2,%3}, {%4,%5,%6,%7}, {%8,%9}, {%0,%1,%2,%3};"
        : "+f"(c[0]), "+f"(c[1]), "+f"(c[2]), "+f"(c[3])
        : "r"(a[0]), "r"(a[1]), "r"(a[2]), "r"(a[3]), "r"(b[0]), "r"(b[1]));
}
__device__ __forceinline__ float gelu(float v) {
    return 0.5f * v * (1.f + erff(v * 0.70710678118654752f));
}
#define CP16(dst, src) \
    asm volatile("cp.async.cg.shared.global [%0], [%1], 16;" :: "r"(dst), "l"(src))
#define CP_COMMIT() asm volatile("cp.async.commit_group;" ::: "memory")
#define CP_WAIT2() asm volatile("cp.async.wait_group 2;" ::: "memory")

// ---------------- fp16 sparse per-expert GEMM, cp.async + ldmatrix ----------------
// EXACT R11 (504us) device code; expert index = ebase + blockIdx.z.
// block 128x128, 128 threads, 2x2 warps (64x64 warp tile), BK=32, 4-stage cp.async
// MODE 1: A = gathered g_Xh rows -> gelu -> g_H (fp16)
// MODE 2: A = g_H rows -> +bias -> g_Y (fp32)
template <int KTOT, int LDB, int MODE>
__global__ void __launch_bounds__(128, 2)
moe_gemm(const __half* __restrict__ Bh, const float* __restrict__ bias, int ebase) {
    constexpr int BK = 32;
    constexpr int KIT = KTOT / BK;
    constexpr int SA_ST = 10240, SB_ST = 8704;
    constexpr int OFF_B = 4 * SA_ST;            // 40960
    constexpr int OFF_TOK = OFF_B + 4 * SB_ST;  // 75776
    extern __shared__ __align__(16) char smem[];
    const uint32_t sbase = smem_u32(smem);

    const int e = ebase + blockIdx.z;
    const int cnt = g_cnt[e];
    const int m0 = blockIdx.y * 128;
    if (m0 >= cnt) return;
    const int n0 = blockIdx.x * 128;
    const int rows = min(cnt - m0, 128);
    const int tid = threadIdx.x, lane = tid & 31, wid = tid >> 5;
    const int wm = wid >> 1, wn = wid & 1;

    int* sTok = (int*)(smem + OFF_TOK);
    if (MODE == 1) {
        if (tid < 128) sTok[tid] = g_list[e * NTOK + m0 + min(tid, rows - 1)];
        __syncthreads();
    }

    const __half* pA[4]; uint32_t aOfs[4];
#pragma unroll
    for (int i = 0; i < 4; i++) {
        int idx = tid + i * 128, r = idx >> 2, c = idx & 3;
        size_t rb;
        if (MODE == 1) rb = (size_t)sTok[r] * DD;
        else           rb = ((size_t)e * NTOK + m0 + r) * FF;
        pA[i] = ((MODE == 1) ? g_Xh : g_H) + rb + c * 8;
        aOfs[i] = (uint32_t)(r * 80 + c * 16);
    }
    const __half* pB[4]; uint32_t bOfs[4];
#pragma unroll
    for (int i = 0; i < 4; i++) {
        int idx = tid + i * 128, k = idx >> 4, c = idx & 15;
        pB[i] = Bh + (size_t)e * KTOT * LDB + (size_t)k * LDB + n0 + c * 8;
        bOfs[i] = (uint32_t)(k * 272 + c * 16);
    }

    uint32_t aFrag[4];
#pragma unroll
    for (int ms = 0; ms < 4; ms++) {
        int row = wm * 64 + ms * 16 + (lane & 7) + ((lane >> 3) & 1) * 8;
        aFrag[ms] = (uint32_t)(row * 80 + ((lane >> 4) & 1) * 16);
    }
    uint32_t bFrag[4];
#pragma unroll
    for (int p = 0; p < 4; p++) {
        int k = (lane & 7) + ((lane >> 3) & 1) * 8;
        int n = wn * 64 + p * 16 + ((lane >> 4) & 1) * 8;
        bFrag[p] = (uint32_t)(k * 272 + n * 2);
    }

    float acc[4][8][4];
#pragma unroll
    for (int a = 0; a < 4; a++)
#pragma unroll
        for (int b = 0; b < 8; b++)
#pragma unroll
            for (int r = 0; r < 4; r++) acc[a][b][r] = 0.f;

    auto fill = [&](int kt) {
        int st = kt & 3;
        uint32_t sa = sbase + st * SA_ST;
        uint32_t sb = sbase + OFF_B + st * SB_ST;
#pragma unroll
        for (int i = 0; i < 4; i++)
            CP16(sa + aOfs[i], pA[i] + (size_t)kt * BK);
#pragma unroll
        for (int i = 0; i < 4; i++)
            CP16(sb + bOfs[i], pB[i] + (size_t)kt * BK * LDB);
    };
    auto compute = [&](int kt) {
        int st = kt & 3;
        uint32_t sa = sbase + st * SA_ST;
        uint32_t sb = sbase + OFF_B + st * SB_ST;
#pragma unroll
        for (int s = 0; s < 2; s++) {
            uint32_t af[4][4], bf[8][2];
#pragma unroll
            for (int ms = 0; ms < 4; ms++) {
                uint32_t addr = sa + aFrag[ms] + s * 32;
                asm volatile(
                    "ldmatrix.sync.aligned.m8n8.x4.shared.b16 {%0,%1,%2,%3}, [%4];"
                    : "=r"(af[ms][0]), "=r"(af[ms][1]),
                      "=r"(af[ms][2]), "=r"(af[ms][3]) : "r"(addr));
            }
#pragma unroll
            for (int p = 0; p < 4; p++) {
                uint32_t addr = sb + bFrag[p] + s * (16 * 272);
                asm volatile(
                    "ldmatrix.sync.aligned.m8n8.x4.trans.shared.b16 {%0,%1,%2,%3}, [%4];"
                    : "=r"(bf[2 * p][0]), "=r"(bf[2 * p][1]),
                      "=r"(bf[2 * p + 1][0]), "=r"(bf[2 * p + 1][1]) : "r"(addr));
            }
#pragma unroll
            for (int ms = 0; ms < 4; ms++)
#pragma unroll
                for (int ns = 0; ns < 8; ns++)
                    mma16(acc[ms][ns], af[ms], bf[ns]);
        }
    };

    fill(0); CP_COMMIT();
    fill(1); CP_COMMIT();
    fill(2); CP_COMMIT();
    for (int kt = 0; kt < KIT; kt++) {
        CP_WAIT2();
        __syncthreads();
        if (kt + 3 < KIT) fill(kt + 3);
        CP_COMMIT();
        compute(kt);
    }

    constexpr int ND = (MODE == 1) ? FF : DD;
    const int lr = lane >> 2, lc = lane & 3;
#pragma unroll
    for (int ms = 0; ms < 4; ms++) {
#pragma unroll
        for (int half = 0; half < 2; half++) {
            int r = wm * 64 + ms * 16 + lr + half * 8;
            if (r >= rows) continue;
            size_t rowb = ((size_t)e * NTOK + m0 + r) * ND;
#pragma unroll
            for (int ns = 0; ns < 8; ns++) {
                int col = n0 + wn * 64 + ns * 8 + lc * 2;
                float2 bv = *(const float2*)&bias[(size_t)e * ND + col];
                float v0 = acc[ms][ns][half * 2 + 0] + bv.x;
                float v1 = acc[ms][ns][half * 2 + 1] + bv.y;
                if (MODE == 1) {
                    v0 = gelu(v0); v1 = gelu(v1);
                    *(__half2*)&g_H[rowb + col] =
                        __halves2half2(__float2half_rn(v0), __float2half_rn(v1));
                } else {
                    *(float2*)&g_Y[rowb + col] = make_float2(v0, v1);
                }
            }
        }
    }
}

// ---------------- combine + expert_counts + counter reset ----------------
__global__ void combine_kernel(float* __restrict__ out, float* __restrict__ counts) {
    int t = blockIdx.x;
    int i = threadIdx.x;
    if (t == 0 && i < NE) {
        if (counts) counts[i] = (float)g_cnt[i];
        g_cnt[i] = 0;
    }
    int p0 = g_cp[t * 2], p1 = g_cp[t * 2 + 1];
    float w0 = g_cw[t * 2], w1 = g_cw[t * 2 + 1];
    const float4* y0 = (const float4*)(g_Y + (size_t)p0 * DD);
    const float4* y1 = (const float4*)(g_Y + (size_t)p1 * DD);
    float4 a = y0[i], b = y1[i], r;
    r.x = w0 * a.x + w1 * b.x;
    r.y = w0 * a.y + w1 * b.y;
    r.z = w0 * a.z + w1 * b.z;
    r.w = w0 * a.w + w1 * b.w;
    ((float4*)(out + (size_t)t * DD))[i] = r;
}

// ---------------- launch: half-split GEMMs, pipelined across 2 chains ----------
extern "C" void kernel_launch(void* const* d_in, const int* in_sizes, int n_in,
                              void* d_out, int out_size) {
    const float* x  = (const float*)d_in[0];
    const float* gw = (const float*)d_in[1];
    const float* gb = (const float*)d_in[2];
    const float* w1 = (const float*)d_in[3];
    const float* b1 = (const float*)d_in[4];
    const float* w2 = (const float*)d_in[5];
    const float* b2 = (const float*)d_in[6];
    float* out = (float*)d_out;

    const long long OUT0 = (long long)NTOK * DD;
    long long os = out_size;
    float* gl = nullptr; float* tk = nullptr; float* cn = nullptr;
    if (os >= OUT0 + (long long)NTOK * NE)
        gl = out + OUT0;
    if (os >= OUT0 + (long long)NTOK * NE + NTOK * 2)
        tk = out + OUT0 + (long long)NTOK * NE;
    if (os >= OUT0 + (long long)NTOK * NE + NTOK * 2 + NE)
        cn = out + OUT0 + (long long)NTOK * NE + NTOK * 2;

    static __half* w1h = nullptr; static __half* w2h = nullptr;
    static cudaStream_t s1, s2;
    static cudaEvent_t evFork, evW1a, evW1b, evW2, ev1a, ev1b, ev2;
    static bool init_done = false;
    if (!init_done) {
        cudaGetSymbolAddress((void**)&w1h, g_W1h);
        cudaGetSymbolAddress((void**)&w2h, g_W2h);
        cudaStreamCreateWithFlags(&s1, cudaStreamNonBlocking);
        cudaStreamCreateWithFlags(&s2, cudaStreamNonBlocking);
        cudaEventCreateWithFlags(&evFork, cudaEventDisableTiming);
        cudaEventCreateWithFlags(&evW1a, cudaEventDisableTiming);
        cudaEventCreateWithFlags(&evW1b, cudaEventDisableTiming);
        cudaEventCreateWithFlags(&evW2, cudaEventDisableTiming);
        cudaEventCreateWithFlags(&ev1a, cudaEventDisableTiming);
        cudaEventCreateWithFlags(&ev1b, cudaEventDisableTiming);
        cudaEventCreateWithFlags(&ev2, cudaEventDisableTiming);
        const int SM_ = 76288;
        cudaFuncSetAttribute(moe_gemm<DD, FF, 1>,
                             cudaFuncAttributeMaxDynamicSharedMemorySize, SM_);
        cudaFuncSetAttribute(moe_gemm<FF, DD, 2>,
                             cudaFuncAttributeMaxDynamicSharedMemorySize, SM_);
        init_done = true;
    }
    const int SMEM = 76288;
    cudaStream_t s0 = 0;

    const long long W1HALF = (long long)(NE / 2) * DD * FF;   // 16M elements
    const dim3 G1(FF / 128, NTOK / 128, NE / 2);
    const dim3 G2(DD / 128, NTOK / 128, NE / 2);

    cudaEventRecord(evFork, s0);
    cudaStreamWaitEvent(s1, evFork, 0);
    cudaStreamWaitEvent(s2, evFork, 0);

    // s1: conversions — w1 in two halves so GEMM1a can start early
    f2h_kernel<<<4096, 256, 0, s1>>>(w1, w1h, (int)(W1HALF / 4));
    cudaEventRecord(evW1a, s1);
    f2h_kernel<<<4096, 256, 0, s1>>>(w1 + W1HALF, w1h + W1HALF, (int)(W1HALF / 4));
    cudaEventRecord(evW1b, s1);
    f2h_kernel<<<8192, 256, 0, s1>>>(w2, w2h, NE * FF * DD / 4);
    cudaEventRecord(evW2, s1);

    // s0: gate, then GEMM1 halves
    gate_kernel<<<NTOK, 256, 0, s0>>>(x, gw, gb, gl, tk);
    cudaStreamWaitEvent(s0, evW1a, 0);
    moe_gemm<DD, FF, 1><<<G1, 128, SMEM, s0>>>(w1h, b1, 0);
    cudaEventRecord(ev1a, s0);
    cudaStreamWaitEvent(s0, evW1b, 0);
    moe_gemm<DD, FF, 1><<<G1, 128, SMEM, s0>>>(w1h, b1, NE / 2);
    cudaEventRecord(ev1b, s0);

    // s2: GEMM2 halves — first half overlaps GEMM1's second half
    cudaStreamWaitEvent(s2, evW2, 0);
    cudaStreamWaitEvent(s2, ev1a, 0);
    moe_gemm<FF, DD, 2><<<G2, 128, SMEM, s2>>>(w2h, b2, 0);
    cudaStreamWaitEvent(s2, ev1b, 0);
    moe_gemm<FF, DD, 2><<<G2, 128, SMEM, s2>>>(w2h, b2, NE / 2);
    cudaEventRecord(ev2, s2);

    // join for combine
    cudaStreamWaitEvent(s0, ev2, 0);
    combine_kernel<<<NTOK, 256, 0, s0>>>(out, cn);
}